// round 16
// baseline (speedup 1.0000x reference)
#include <cuda_runtime.h>
#include <cuda_fp16.h>
#include <cstdint>
#include <cstddef>

// ---------------- scratch (no allocs allowed) ----------------
#define O_CAP 100000
static __device__ float g_pooled[(size_t)O_CAP * 128];
static __device__ float g_counts[O_CAP];
static __device__ __half g_proj[(size_t)O_CAP * 256];   // half: 50MB -> L2-resident
// 8 pre-transposed half tiles [n=128][k=128]:
// 0,1,2: w1a k-rows [0:128),[128:256),[256:384);  3,4,5: w1b nc 0..2;  6: w2a; 7: w2b
static __device__ __half g_wt[8 * 128 * 128];

#define PADK  68   // As row stride (words): 64 data + 4 pad -> conflict-free, 272B = 17*16
#define PADW2 36   // half-K W row stride (words): 32 data + 4 pad -> conflict-free, 144B = 9*16
#define PADPR 68   // staged proj row stride (words)
#define MT    64   // rows per block (triple & proj)

// ---------------- helpers ----------------
__device__ __forceinline__ unsigned pk2(float x, float y) {
    __half2 h = __floats2half2_rn(x, y);
    return *reinterpret_cast<unsigned*>(&h);
}
__device__ __forceinline__ void mma_f16(float c[4], const unsigned a[4], const unsigned b[2]) {
    asm volatile(
        "mma.sync.aligned.m16n8k16.row.col.f32.f16.f16.f32 "
        "{%0,%1,%2,%3},{%4,%5,%6,%7},{%8,%9},{%0,%1,%2,%3};\n"
        : "+f"(c[0]), "+f"(c[1]), "+f"(c[2]), "+f"(c[3])
        : "r"(a[0]), "r"(a[1]), "r"(a[2]), "r"(a[3]), "r"(b[0]), "r"(b[1]));
}
__device__ __forceinline__ void ldsm_x4(unsigned r[4], const unsigned* p) {
    unsigned addr = (unsigned)__cvta_generic_to_shared(p);
    asm volatile("ldmatrix.sync.aligned.m8n8.x4.shared.b16 {%0,%1,%2,%3}, [%4];"
                 : "=r"(r[0]), "=r"(r[1]), "=r"(r[2]), "=r"(r[3]) : "r"(addr));
}
__device__ __forceinline__ void red_add_v4(float* p, float a, float b, float c, float d) {
    asm volatile("red.global.add.v4.f32 [%0], {%1,%2,%3,%4};"
                 :: "l"(p), "f"(a), "f"(b), "f"(c), "f"(d) : "memory");
}
__device__ __forceinline__ void cp16(void* dst, const void* src) {
    unsigned d = (unsigned)__cvta_generic_to_shared(dst);
    asm volatile("cp.async.cg.shared.global [%0], [%1], 16;" :: "r"(d), "l"(src) : "memory");
}
#define CP_COMMIT() asm volatile("cp.async.commit_group;" ::: "memory")
#define CP_WAIT0()  asm volatile("cp.async.wait_group 0;" ::: "memory")

// ================= prep: transpose+convert weights to half [n][k] =================
__global__ void prep_kernel(const float* __restrict__ w1a, const float* __restrict__ w1b,
                            const float* __restrict__ w2a, const float* __restrict__ w2b,
                            __half* __restrict__ wt)
{
    const int t = blockIdx.x;           // 0..7
    const int tid = threadIdx.x;
    for (int p = 0; p < 64; p++) {
        int idx = p * 256 + tid;        // 0..16383
        int n = idx >> 7, k = idx & 127;
        float v;
        if (t < 3)       v = w1a[(size_t)(t * 128 + k) * 128 + n];
        else if (t < 6)  v = w1b[(size_t)k * 384 + (t - 3) * 128 + n];
        else if (t == 6) v = w2a[(size_t)k * 128 + n];
        else             v = w2b[(size_t)k * 128 + n];
        wt[((size_t)t * 128 + n) * 128 + k] = __float2half_rn(v);
    }
}

// ================= Kernel A: triple MLP, fused GEMM1 epilogue =================
__global__ __launch_bounds__(256, 3)
void triple_kernel(const float* __restrict__ predi, const int* __restrict__ edges,
                   const __half* __restrict__ wt,
                   const float* __restrict__ b1a, const float* __restrict__ b1b,
                   const __half* __restrict__ proj,
                   float* __restrict__ outP, float* __restrict__ pooled,
                   float* __restrict__ counts, int T)
{
    extern __shared__ unsigned smu[];
    unsigned* As = smu;                            // MT*PADK
    unsigned* Wb = smu + MT * PADK;                // 2 * 128*PADW2 ; buf0 also stages proj_o
    unsigned* Pr = Wb + 2 * 128 * PADW2;           // MT*PADPR : proj_s rows
    int* sIdx = (int*)(Pr + MT * PADPR);
    int* oIdx = sIdx + MT;

    const int tid  = threadIdx.x;
    const int lane = tid & 31;
    const int g    = lane >> 2;
    const int tg   = lane & 3;
    const int w    = tid >> 5;
    const int R0   = (w >> 2) * 32;
    const int C0   = (w & 3) * 32;
    const int t0   = blockIdx.x * MT;

    const int rp   = lane & 7;
    const int sel  = lane >> 3;
    const int arow = ((sel & 1) << 3) + rp;
    const int acol = (sel >> 1) << 2;
    const int brow = ((sel >> 1) << 3) + rp;
    const int bcol = (sel & 1) << 2;

    auto stageW = [&](int buf, const __half* tile, int half) {
        unsigned* dstBase = Wb + buf * 128 * PADW2;
#pragma unroll
        for (int p = 0; p < 4; p++) {
            int idx = p * 256 + tid;
            int n = idx >> 3, c8 = idx & 7;
            cp16(dstBase + n * PADW2 + c8 * 4, tile + n * 128 + half * 64 + c8 * 8);
        }
        CP_COMMIT();
    };

    auto stageProj = [&](unsigned* dst, const int* ridx, int off) {
#pragma unroll
        for (int p = 0; p < 4; p++) {
            int idx = p * 256 + tid;
            int row = idx >> 4, seg = idx & 15;
            cp16(dst + row * PADPR + seg * 4,
                 proj + (size_t)ridx[row] * 256 + off + seg * 8);
        }
        CP_COMMIT();
    };

    stageW(0, wt + 1 * 16384, 0);                  // chunk0: GEMM1 half0

    if (tid < MT) {
        int t = t0 + tid;
        int s = 0, o = 0;
        if (t < T) {
            s = edges[2 * t];
            o = edges[2 * t + 1];
            atomicAdd(&counts[s], 1.0f);
            atomicAdd(&counts[o], 1.0f);
        }
        sIdx[tid] = s; oIdx[tid] = o;
    }

#pragma unroll
    for (int p = 0; p < 8; p++) {
        int idx = p * 256 + tid;
        int r = idx >> 5, c4 = idx & 31;
        int t = t0 + r;
        float4 v = make_float4(0.f, 0.f, 0.f, 0.f);
        if (t < T) v = *(const float4*)(predi + (size_t)t * 128 + c4 * 4);
        *(uint2*)(As + r * PADK + c4 * 2) = make_uint2(pk2(v.x, v.y), pk2(v.z, v.w));
    }
    CP_WAIT0();
    __syncthreads();                               // A + chunk0 ready; sIdx/oIdx visible

    float acc[2][4][4];
#pragma unroll
    for (int mi = 0; mi < 2; mi++)
#pragma unroll
        for (int ni = 0; ni < 4; ni++)
#pragma unroll
            for (int q = 0; q < 4; q++) acc[mi][ni][q] = 0.f;

    auto mmaChunk = [&](int b, int kwA0) {
        const unsigned* Wu = Wb + b * 128 * PADW2;
#pragma unroll
        for (int ks = 0; ks < 4; ks++) {
            const int kwA = kwA0 + ks * 8;
            const int kwB = ks * 8;
            unsigned a[2][4], bb[2][4];
#pragma unroll
            for (int mi = 0; mi < 2; mi++)
                ldsm_x4(a[mi], As + (R0 + mi * 16 + arow) * PADK + kwA + acol);
#pragma unroll
            for (int j = 0; j < 2; j++)
                ldsm_x4(bb[j], Wu + (C0 + j * 16 + brow) * PADW2 + kwB + bcol);
#pragma unroll
            for (int mi = 0; mi < 2; mi++)
#pragma unroll
                for (int ni = 0; ni < 4; ni++)
                    mma_f16(acc[mi][ni], a[mi], &bb[ni >> 1][(ni & 1) * 2]);
        }
    };

    // ---------------- GEMM1 ----------------
    // i=0: stage chunk1 + proj_s(Pr); mma chunk0
    stageW(1, wt + 1 * 16384, 1);
    stageProj(Pr, sIdx, 0);
    mmaChunk(0, 0);
    CP_WAIT0();
    __syncthreads();

    // i=1: stage proj_o into dead buf0; mma chunk1
    stageProj(Wb, oIdx, 128);
    mmaChunk(1, 32);
    CP_WAIT0();
    __syncthreads();

    // fused epilogue: stage chunk2 into buf1 (chunk1 consumed); H = relu(acc+b1a+s+o)
    stageW(1, wt + 3 * 16384, 0);
#pragma unroll
    for (int mi = 0; mi < 2; mi++) {
        int ra = R0 + mi * 16 + g;
        int rb = ra + 8;
#pragma unroll
        for (int ni = 0; ni < 4; ni++) {
            int c = C0 + ni * 8 + 2 * tg;
            float2 bv = *(const float2*)(b1a + c);
            float2 sa = __half22float2(*(const __half2*)(Pr + ra * PADPR + (c >> 1)));
            float2 sb = __half22float2(*(const __half2*)(Pr + rb * PADPR + (c >> 1)));
            float2 oa = __half22float2(*(const __half2*)(Wb + ra * PADPR + (c >> 1)));
            float2 ob = __half22float2(*(const __half2*)(Wb + rb * PADPR + (c >> 1)));
            As[ra * PADK + (c >> 1)] = pk2(fmaxf(acc[mi][ni][0] + bv.x + sa.x + oa.x, 0.f),
                                           fmaxf(acc[mi][ni][1] + bv.y + sa.y + oa.y, 0.f));
            As[rb * PADK + (c >> 1)] = pk2(fmaxf(acc[mi][ni][2] + bv.x + sb.x + ob.x, 0.f),
                                           fmaxf(acc[mi][ni][3] + bv.y + sb.y + ob.y, 0.f));
        }
    }
    CP_WAIT0();
    __syncthreads();                               // H visible; chunk2 ready; proj dead
#pragma unroll
    for (int mi = 0; mi < 2; mi++)
#pragma unroll
        for (int ni = 0; ni < 4; ni++)
#pragma unroll
            for (int q = 0; q < 4; q++) acc[mi][ni][q] = 0.f;

    // ---------------- GEMM2: chunks 2..7 ----------------
    for (int i = 2; i < 8; i++) {
        const int b = (i & 1) ^ 1;                 // chunk2->buf1, chunk3->buf0, ...
        if (i < 7)
            stageW(b ^ 1, wt + (size_t)(3 + ((i - 1) >> 1)) * 16384, (i + 1) & 1);
        mmaChunk(b, (i & 1) * 32);
        CP_WAIT0();
        __syncthreads();

        if (i & 1) {
            const int nc = (i - 2) >> 1;
            const int boff = nc * 128;
#pragma unroll
            for (int mi = 0; mi < 2; mi++) {
                int ra = R0 + mi * 16 + g;
                int rb = ra + 8;
                int ta = t0 + ra, tb = t0 + rb;
                float* dA;
                float* dB;
                if (nc == 1) { dA = outP + (size_t)ta * 128; dB = outP + (size_t)tb * 128; }
                else {
                    const int* ridx = nc ? oIdx : sIdx;
                    dA = pooled + (size_t)ridx[ra] * 128;
                    dB = pooled + (size_t)ridx[rb] * 128;
                }
#pragma unroll
                for (int ni = 0; ni < 4; ni++) {
                    int cb = C0 + ni * 8;
                    float2 bv = *(const float2*)(b1b + boff + cb + 2 * tg);
                    float p0 = fmaxf(acc[mi][ni][0] + bv.x, 0.f);
                    float p1 = fmaxf(acc[mi][ni][1] + bv.y, 0.f);
                    float q0 = fmaxf(acc[mi][ni][2] + bv.x, 0.f);
                    float q1 = fmaxf(acc[mi][ni][3] + bv.y, 0.f);
                    float pp0 = __shfl_xor_sync(0xFFFFFFFF, p0, 1);
                    float pp1 = __shfl_xor_sync(0xFFFFFFFF, p1, 1);
                    float qq0 = __shfl_xor_sync(0xFFFFFFFF, q0, 1);
                    float qq1 = __shfl_xor_sync(0xFFFFFFFF, q1, 1);
                    if (nc == 1) {
                        if (!(tg & 1)) {
                            if (ta < T) *(float4*)(dA + cb + 2 * tg) = make_float4(p0, p1, pp0, pp1);
                        } else {
                            if (tb < T) *(float4*)(dB + cb + 2 * (tg - 1)) = make_float4(qq0, qq1, q0, q1);
                        }
                    } else {
                        if (!(tg & 1)) {
                            if (ta < T) red_add_v4(dA + cb + 2 * tg, p0, p1, pp0, pp1);
                        } else {
                            if (tb < T) red_add_v4(dB + cb + 2 * (tg - 1), qq0, qq1, q0, q1);
                        }
                    }
                }
            }
            if (i < 7) {
#pragma unroll
                for (int mi = 0; mi < 2; mi++)
#pragma unroll
                    for (int ni = 0; ni < 4; ni++)
#pragma unroll
                        for (int q = 0; q < 4; q++) acc[mi][ni][q] = 0.f;
            }
        }
    }
}

// ================= Kernel P: proj (R14, frozen) =================
__global__ __launch_bounds__(256, 3)
void proj_kernel(const float* __restrict__ obj, const __half* __restrict__ wt,
                 __half* __restrict__ proj, int O)
{
    extern __shared__ unsigned smu[];
    unsigned* As = smu;
    unsigned* Wb = smu + MT * PADK;

    const int tid  = threadIdx.x;
    const int lane = tid & 31;
    const int g    = lane >> 2;
    const int tg   = lane & 3;
    const int w    = tid >> 5;
    const int R0   = (w >> 2) * 32;
    const int C0   = (w & 3) * 32;
    const int o0   = blockIdx.x * MT;

    const int rp   = lane & 7;
    const int sel  = lane >> 3;
    const int arow = ((sel & 1) << 3) + rp;
    const int acol = (sel >> 1) << 2;
    const int brow = ((sel >> 1) << 3) + rp;
    const int bcol = (sel & 1) << 2;

    auto stageW = [&](int buf, const __half* tile, int half) {
        unsigned* dstBase = Wb + buf * 128 * PADW2;
#pragma unroll
        for (int p = 0; p < 4; p++) {
            int idx = p * 256 + tid;
            int n = idx >> 3, c8 = idx & 7;
            cp16(dstBase + n * PADW2 + c8 * 4, tile + n * 128 + half * 64 + c8 * 8);
        }
        CP_COMMIT();
    };

    stageW(0, wt, 0);

#pragma unroll
    for (int p = 0; p < 8; p++) {
        int idx = p * 256 + tid;
        int r = idx >> 5, c4 = idx & 31;
        int o = o0 + r;
        float4 v = make_float4(0.f, 0.f, 0.f, 0.f);
        if (o < O) v = *(const float4*)(obj + (size_t)o * 128 + c4 * 4);
        *(uint2*)(As + r * PADK + c4 * 2) = make_uint2(pk2(v.x, v.y), pk2(v.z, v.w));
    }
    CP_WAIT0();
    __syncthreads();

    float acc[2][4][4];
#pragma unroll
    for (int mi = 0; mi < 2; mi++)
#pragma unroll
        for (int ni = 0; ni < 4; ni++)
#pragma unroll
            for (int q = 0; q < 4; q++) acc[mi][ni][q] = 0.f;

    auto mmaChunk = [&](int b, int kwA0) {
        const unsigned* Wu = Wb + b * 128 * PADW2;
#pragma unroll
        for (int ks = 0; ks < 4; ks++) {
            const int kwA = kwA0 + ks * 8;
            const int kwB = ks * 8;
            unsigned a[2][4], bb[2][4];
#pragma unroll
            for (int mi = 0; mi < 2; mi++)
                ldsm_x4(a[mi], As + (R0 + mi * 16 + arow) * PADK + kwA + acol);
#pragma unroll
            for (int j = 0; j < 2; j++)
                ldsm_x4(bb[j], Wu + (C0 + j * 16 + brow) * PADW2 + kwB + bcol);
#pragma unroll
            for (int mi = 0; mi < 2; mi++)
#pragma unroll
                for (int ni = 0; ni < 4; ni++)
                    mma_f16(acc[mi][ni], a[mi], &bb[ni >> 1][(ni & 1) * 2]);
        }
    };

    for (int i = 0; i < 4; i++) {
        if (i < 3) {
            const __half* tile2 = (i + 1) < 2 ? wt : wt + 2 * 16384;
            stageW((i + 1) & 1, tile2, (i + 1) & 1);
        }
        mmaChunk(i & 1, (i & 1) * 32);
        CP_WAIT0();
        __syncthreads();

        if (i & 1) {
            const int m = i >> 1;
#pragma unroll
            for (int mi = 0; mi < 2; mi++) {
                int ra = R0 + mi * 16 + g;
                int rb = ra + 8;
                int oa = o0 + ra, ob = o0 + rb;
#pragma unroll
                for (int ni = 0; ni < 4; ni++) {
                    int cb = C0 + ni * 8;
                    float p0 = acc[mi][ni][0], p1 = acc[mi][ni][1];
                    float q0 = acc[mi][ni][2], q1 = acc[mi][ni][3];
                    float pp0 = __shfl_xor_sync(0xFFFFFFFF, p0, 1);
                    float pp1 = __shfl_xor_sync(0xFFFFFFFF, p1, 1);
                    float qq0 = __shfl_xor_sync(0xFFFFFFFF, q0, 1);
                    float qq1 = __shfl_xor_sync(0xFFFFFFFF, q1, 1);
                    if (!(tg & 1)) {
                        if (oa < O)
                            *(uint2*)(proj + (size_t)oa * 256 + m * 128 + cb + 2 * tg) =
                                make_uint2(pk2(p0, p1), pk2(pp0, pp1));
                    } else {
                        if (ob < O)
                            *(uint2*)(proj + (size_t)ob * 256 + m * 128 + cb + 2 * (tg - 1)) =
                                make_uint2(pk2(qq0, qq1), pk2(q0, q1));
                    }
                }
            }
            if (i < 3) {
#pragma unroll
                for (int mi = 0; mi < 2; mi++)
#pragma unroll
                    for (int ni = 0; ni < 4; ni++)
#pragma unroll
                        for (int q = 0; q < 4; q++) acc[mi][ni][q] = 0.f;
            }
        }
    }
}

// ---------------- shared m32n64 mainloop for obj (ldmatrix) ----------------
#define MMA_KLOOP(As, Wu, acc, R0, C0, arow, acol, brow, bcol)                  \
    do {                                                                        \
        _Pragma("unroll")                                                       \
        for (int ks = 0; ks < 8; ks++) {                                        \
            const int kw = ks * 8;                                              \
            unsigned a[2][4], bb[4][4];                                         \
            _Pragma("unroll")                                                   \
            for (int mi = 0; mi < 2; mi++)                                      \
                ldsm_x4(a[mi], (As) + ((R0) + mi * 16 + (arow)) * PADK + kw + (acol)); \
            _Pragma("unroll")                                                   \
            for (int j = 0; j < 4; j++)                                         \
                ldsm_x4(bb[j], (Wu) + ((C0) + j * 16 + (brow)) * PADK + kw + (bcol)); \
            _Pragma("unroll")                                                   \
            for (int mi = 0; mi < 2; mi++)                                      \
                _Pragma("unroll")                                               \
                for (int ni = 0; ni < 8; ni++)                                  \
                    mma_f16(acc[mi][ni], a[mi], &bb[ni >> 1][(ni & 1) * 2]);    \
        }                                                                       \
    } while (0)

#define ZERO_ACC8(acc)                                                          \
    do {                                                                        \
        _Pragma("unroll")                                                       \
        for (int mi = 0; mi < 2; mi++)                                          \
            _Pragma("unroll")                                                   \
            for (int ni = 0; ni < 8; ni++)                                      \
                _Pragma("unroll")                                               \
                for (int q = 0; q < 4; q++) acc[mi][ni][q] = 0.f;               \
    } while (0)

// ================= Kernel B: object MLP (R14 m32n64/occ2, restored) =================
__global__ __launch_bounds__(256, 2)
void obj_kernel(const __half* __restrict__ wt,
                const float* __restrict__ b2a, const float* __restrict__ b2b,
                const float* __restrict__ pooled, const float* __restrict__ counts,
                float* __restrict__ outO, int O)
{
    extern __shared__ unsigned smu[];
    unsigned* As = smu;
    unsigned* Wu = smu + 128 * PADK;
    float* invc = (float*)(smu + 2 * 128 * PADK);

    const int tid  = threadIdx.x;
    const int lane = tid & 31;
    const int g    = lane >> 2;
    const int tg   = lane & 3;
    const int w    = tid >> 5;
    const int R0   = (w >> 1) * 32;
    const int C0   = (w & 1) * 64;
    const int o0   = blockIdx.x * 128;

    const int rp   = lane & 7;
    const int sel  = lane >> 3;
    const int arow = ((sel & 1) << 3) + rp;
    const int acol = (sel >> 1) << 2;
    const int brow = ((sel >> 1) << 3) + rp;
    const int bcol = (sel & 1) << 2;

    if (tid < 128) {
        int o = o0 + tid;
        float c = (o < O) ? counts[o] : 1.f;
        c = fminf(fmaxf(c, 1.f), 1000.f);
        invc[tid] = 1.f / c;
    }

    auto stageW = [&](const __half* src) {
        const uint4* s = (const uint4*)src;
#pragma unroll
        for (int p = 0; p < 8; p++) {
            int idx = p * 256 + tid;
            int n = idx >> 4, c = idx & 15;
            *(uint4*)(Wu + n * PADK + c * 4) = s[idx];
        }
    };

    stageW(wt + 6 * 16384);                // w2a^T
    __syncthreads();

#pragma unroll
    for (int p = 0; p < 16; p++) {
        int idx = p * 256 + tid;
        int r = idx >> 5, c4 = idx & 31;
        int o = o0 + r;
        float4 v = make_float4(0.f, 0.f, 0.f, 0.f);
        if (o < O) v = *(const float4*)(pooled + (size_t)o * 128 + c4 * 4);
        float s = invc[r];
        *(uint2*)(As + r * PADK + c4 * 2) =
            make_uint2(pk2(v.x * s, v.y * s), pk2(v.z * s, v.w * s));
    }
    __syncthreads();

    float acc[2][8][4];
    ZERO_ACC8(acc);
    MMA_KLOOP(As, Wu, acc, R0, C0, arow, acol, brow, bcol);
    __syncthreads();

#pragma unroll
    for (int mi = 0; mi < 2; mi++) {
        int ra = R0 + mi * 16 + g;
        int rb = ra + 8;
#pragma unroll
        for (int ni = 0; ni < 8; ni++) {
            int c = C0 + ni * 8 + 2 * tg;
            float2 bv = *(const float2*)(b2a + c);
            As[ra * PADK + (c >> 1)] = pk2(fmaxf(acc[mi][ni][0] + bv.x, 0.f),
                                           fmaxf(acc[mi][ni][1] + bv.y, 0.f));
            As[rb * PADK + (c >> 1)] = pk2(fmaxf(acc[mi][ni][2] + bv.x, 0.f),
                                           fmaxf(acc[mi][ni][3] + bv.y, 0.f));
        }
    }
    stageW(wt + 7 * 16384);
    __syncthreads();

    ZERO_ACC8(acc);
    MMA_KLOOP(As, Wu, acc, R0, C0, arow, acol, brow, bcol);
#pragma unroll
    for (int mi = 0; mi < 2; mi++) {
        int ra = R0 + mi * 16 + g;
        int rb = ra + 8;
        int oa = o0 + ra, ob = o0 + rb;
#pragma unroll
        for (int ni = 0; ni < 8; ni++) {
            int cb = C0 + ni * 8;
            float2 bv = *(const float2*)(b2b + cb + 2 * tg);
            float p0 = fmaxf(acc[mi][ni][0] + bv.x, 0.f);
            float p1 = fmaxf(acc[mi][ni][1] + bv.y, 0.f);
            float q0 = fmaxf(acc[mi][ni][2] + bv.x, 0.f);
            float q1 = fmaxf(acc[mi][ni][3] + bv.y, 0.f);
            float pp0 = __shfl_xor_sync(0xFFFFFFFF, p0, 1);
            float pp1 = __shfl_xor_sync(0xFFFFFFFF, p1, 1);
            float qq0 = __shfl_xor_sync(0xFFFFFFFF, q0, 1);
            float qq1 = __shfl_xor_sync(0xFFFFFFFF, q1, 1);
            if (!(tg & 1)) {
                if (oa < O)
                    *(float4*)(outO + (size_t)oa * 128 + cb + 2 * tg) =
                        make_float4(p0, p1, pp0, pp1);
            } else {
                if (ob < O)
                    *(float4*)(outO + (size_t)ob * 128 + cb + 2 * (tg - 1)) =
                        make_float4(qq0, qq1, q0, q1);
            }
        }
    }
}

// ================= launch =================
extern "C" void kernel_launch(void* const* d_in, const int* in_sizes, int n_in,
                              void* d_out, int out_size)
{
    const float* obj   = (const float*)d_in[0];
    const float* predi = (const float*)d_in[1];
    const int*   edges = (const int*)d_in[2];
    const float* w1a   = (const float*)d_in[3];
    const float* b1a   = (const float*)d_in[4];
    const float* w1b   = (const float*)d_in[5];
    const float* b1b   = (const float*)d_in[6];
    const float* w2a   = (const float*)d_in[7];
    const float* b2a   = (const float*)d_in[8];
    const float* w2b   = (const float*)d_in[9];
    const float* b2b   = (const float*)d_in[10];

    const int O = in_sizes[0] / 128;
    const int T = in_sizes[1] / 128;

    float* outO = (float*)d_out;
    float* outP = outO + (size_t)O * 128;

    float *pooled = nullptr, *counts = nullptr;
    __half *proj = nullptr, *wt = nullptr;
    cudaGetSymbolAddress((void**)&pooled, g_pooled);
    cudaGetSymbolAddress((void**)&counts, g_counts);
    cudaGetSymbolAddress((void**)&proj,   g_proj);
    cudaGetSymbolAddress((void**)&wt,     g_wt);

    cudaMemsetAsync(pooled, 0, (size_t)O * 128 * sizeof(float));
    cudaMemsetAsync(counts, 0, (size_t)O * sizeof(float));

    const size_t smT = (size_t)(MT * PADK + 2 * 128 * PADW2 + MT * PADPR) * 4
                     + MT * 2 * 4 + 256;
    const size_t smP = (size_t)(MT * PADK + 2 * 128 * PADW2) * 4 + 256;
    const size_t smB = (size_t)(2 * 128 * PADK) * 4 + 512;

    cudaFuncSetAttribute(proj_kernel,   cudaFuncAttributeMaxDynamicSharedMemorySize, (int)smP);
    cudaFuncSetAttribute(triple_kernel, cudaFuncAttributeMaxDynamicSharedMemorySize, (int)smT);
    cudaFuncSetAttribute(obj_kernel,    cudaFuncAttributeMaxDynamicSharedMemorySize, (int)smB);

    prep_kernel<<<8, 256>>>(w1a, w1b, w2a, w2b, wt);
    proj_kernel<<<(O + MT - 1) / MT, 256, smP>>>(obj, wt, proj, O);
    triple_kernel<<<(T + MT - 1) / MT, 256, smT>>>(predi, edges, wt, b1a, b1b, proj,
                                                   outP, pooled, counts, T);
    obj_kernel<<<(O + 127) / 128, 256, smB>>>(wt, b2a, b2b, pooled, counts, outO, O);
}

// round 17
// speedup vs baseline: 1.0355x; 1.0355x over previous
#include <cuda_runtime.h>
#include <cuda_fp16.h>
#include <cstdint>
#include <cstddef>

// ---------------- scratch (no allocs allowed) ----------------
#define O_CAP 100000
static __device__ float g_pooled[(size_t)O_CAP * 128];
static __device__ float g_counts[O_CAP];
static __device__ __half g_proj[(size_t)O_CAP * 256];   // half: 50MB -> L2-resident
// 8 pre-transposed half tiles [n=128][k=128]:
// 0,1,2: w1a k-rows [0:128),[128:256),[256:384);  3,4,5: w1b nc 0..2;  6: w2a; 7: w2b
static __device__ __half g_wt[8 * 128 * 128];

#define PADK  68   // As row stride (words): 64 data + 4 pad -> conflict-free, 272B = 17*16
#define PADW2 36   // half-K W row stride (words): 32 data + 4 pad -> conflict-free, 144B = 9*16
#define PADPR 68   // staged proj row stride (words)
#define MT    64   // rows per block (triple & proj)

// ---------------- helpers ----------------
__device__ __forceinline__ unsigned pk2(float x, float y) {
    __half2 h = __floats2half2_rn(x, y);
    return *reinterpret_cast<unsigned*>(&h);
}
__device__ __forceinline__ void mma_f16(float c[4], const unsigned a[4], const unsigned b[2]) {
    asm volatile(
        "mma.sync.aligned.m16n8k16.row.col.f32.f16.f16.f32 "
        "{%0,%1,%2,%3},{%4,%5,%6,%7},{%8,%9},{%0,%1,%2,%3};\n"
        : "+f"(c[0]), "+f"(c[1]), "+f"(c[2]), "+f"(c[3])
        : "r"(a[0]), "r"(a[1]), "r"(a[2]), "r"(a[3]), "r"(b[0]), "r"(b[1]));
}
__device__ __forceinline__ void ldsm_x4(unsigned r[4], const unsigned* p) {
    unsigned addr = (unsigned)__cvta_generic_to_shared(p);
    asm volatile("ldmatrix.sync.aligned.m8n8.x4.shared.b16 {%0,%1,%2,%3}, [%4];"
                 : "=r"(r[0]), "=r"(r[1]), "=r"(r[2]), "=r"(r[3]) : "r"(addr));
}
__device__ __forceinline__ void red_add_v4(float* p, float a, float b, float c, float d) {
    asm volatile("red.global.add.v4.f32 [%0], {%1,%2,%3,%4};"
                 :: "l"(p), "f"(a), "f"(b), "f"(c), "f"(d) : "memory");
}
__device__ __forceinline__ void cp16(void* dst, const void* src) {
    unsigned d = (unsigned)__cvta_generic_to_shared(dst);
    asm volatile("cp.async.cg.shared.global [%0], [%1], 16;" :: "r"(d), "l"(src) : "memory");
}
#define CP_COMMIT() asm volatile("cp.async.commit_group;" ::: "memory")
#define CP_WAIT0()  asm volatile("cp.async.wait_group 0;" ::: "memory")

// ================= prep: transpose+convert weights to half [n][k] =================
__global__ void prep_kernel(const float* __restrict__ w1a, const float* __restrict__ w1b,
                            const float* __restrict__ w2a, const float* __restrict__ w2b,
                            __half* __restrict__ wt)
{
    const int t = blockIdx.x;           // 0..7
    const int tid = threadIdx.x;
    for (int p = 0; p < 64; p++) {
        int idx = p * 256 + tid;        // 0..16383
        int n = idx >> 7, k = idx & 127;
        float v;
        if (t < 3)       v = w1a[(size_t)(t * 128 + k) * 128 + n];
        else if (t < 6)  v = w1b[(size_t)k * 384 + (t - 3) * 128 + n];
        else if (t == 6) v = w2a[(size_t)k * 128 + n];
        else             v = w2b[(size_t)k * 128 + n];
        wt[((size_t)t * 128 + n) * 128 + k] = __float2half_rn(v);
    }
}

// ================= Kernel A: triple MLP (R14 schedule, dead final barrier removed) =================
__global__ __launch_bounds__(256, 3)
void triple_kernel(const float* __restrict__ predi, const int* __restrict__ edges,
                   const __half* __restrict__ wt,
                   const float* __restrict__ b1a, const float* __restrict__ b1b,
                   const __half* __restrict__ proj,
                   float* __restrict__ outP, float* __restrict__ pooled,
                   float* __restrict__ counts, int T)
{
    extern __shared__ unsigned smu[];
    unsigned* As = smu;                            // MT*PADK
    unsigned* Wb = smu + MT * PADK;                // 2 * 128*PADW2 ; buf0 also stages proj rows
    int* sIdx = (int*)(smu + MT * PADK + 2 * 128 * PADW2);
    int* oIdx = sIdx + MT;

    const int tid  = threadIdx.x;
    const int lane = tid & 31;
    const int g    = lane >> 2;
    const int tg   = lane & 3;
    const int w    = tid >> 5;
    const int R0   = (w >> 2) * 32;
    const int C0   = (w & 3) * 32;
    const int t0   = blockIdx.x * MT;

    const int rp   = lane & 7;
    const int sel  = lane >> 3;
    const int arow = ((sel & 1) << 3) + rp;
    const int acol = (sel >> 1) << 2;
    const int brow = ((sel >> 1) << 3) + rp;
    const int bcol = (sel & 1) << 2;

    auto stageW = [&](int buf, const __half* tile, int half) {
        unsigned* dstBase = Wb + buf * 128 * PADW2;
#pragma unroll
        for (int p = 0; p < 4; p++) {
            int idx = p * 256 + tid;
            int n = idx >> 3, c8 = idx & 7;
            cp16(dstBase + n * PADW2 + c8 * 4, tile + n * 128 + half * 64 + c8 * 8);
        }
        CP_COMMIT();
    };

    auto stageProj = [&](const int* ridx, int off) {
#pragma unroll
        for (int p = 0; p < 4; p++) {
            int idx = p * 256 + tid;
            int row = idx >> 4, seg = idx & 15;
            cp16(Wb + row * PADPR + seg * 4,
                 proj + (size_t)ridx[row] * 256 + off + seg * 8);
        }
        CP_COMMIT();
    };

    stageW(0, wt + 1 * 16384, 0);

    if (tid < MT) {
        int t = t0 + tid;
        int s = 0, o = 0;
        if (t < T) {
            s = edges[2 * t];
            o = edges[2 * t + 1];
            atomicAdd(&counts[s], 1.0f);
            atomicAdd(&counts[o], 1.0f);
        }
        sIdx[tid] = s; oIdx[tid] = o;
    }

#pragma unroll
    for (int p = 0; p < 8; p++) {
        int idx = p * 256 + tid;
        int r = idx >> 5, c4 = idx & 31;
        int t = t0 + r;
        float4 v = make_float4(0.f, 0.f, 0.f, 0.f);
        if (t < T) v = *(const float4*)(predi + (size_t)t * 128 + c4 * 4);
        *(uint2*)(As + r * PADK + c4 * 2) = make_uint2(pk2(v.x, v.y), pk2(v.z, v.w));
    }
    CP_WAIT0();
    __syncthreads();

    float acc[2][4][4];
#pragma unroll
    for (int mi = 0; mi < 2; mi++)
#pragma unroll
        for (int ni = 0; ni < 4; ni++)
#pragma unroll
            for (int q = 0; q < 4; q++) acc[mi][ni][q] = 0.f;

    auto mmaChunk = [&](int b, int kwA0) {
        const unsigned* Wu = Wb + b * 128 * PADW2;
#pragma unroll
        for (int ks = 0; ks < 4; ks++) {
            const int kwA = kwA0 + ks * 8;
            const int kwB = ks * 8;
            unsigned a[2][4], bb[2][4];
#pragma unroll
            for (int mi = 0; mi < 2; mi++)
                ldsm_x4(a[mi], As + (R0 + mi * 16 + arow) * PADK + kwA + acol);
#pragma unroll
            for (int j = 0; j < 2; j++)
                ldsm_x4(bb[j], Wu + (C0 + j * 16 + brow) * PADW2 + kwB + bcol);
#pragma unroll
            for (int mi = 0; mi < 2; mi++)
#pragma unroll
                for (int ni = 0; ni < 4; ni++)
                    mma_f16(acc[mi][ni], a[mi], &bb[ni >> 1][(ni & 1) * 2]);
        }
    };

    // GEMM1
    stageW(1, wt + 1 * 16384, 1);
    mmaChunk(0, 0);
    CP_WAIT0();
    __syncthreads();

    stageProj(sIdx, 0);
    mmaChunk(1, 32);
    CP_WAIT0();
    __syncthreads();

    // phase A: acc += bias + proj_s; overlap chunk2 prefetch
    stageW(1, wt + 3 * 16384, 0);
#pragma unroll
    for (int mi = 0; mi < 2; mi++) {
        int ra = R0 + mi * 16 + g;
        int rb = ra + 8;
#pragma unroll
        for (int ni = 0; ni < 4; ni++) {
            int c = C0 + ni * 8 + 2 * tg;
            float2 bv = *(const float2*)(b1a + c);
            float2 sa = __half22float2(*(const __half2*)(Wb + ra * PADPR + (c >> 1)));
            float2 sb = __half22float2(*(const __half2*)(Wb + rb * PADPR + (c >> 1)));
            acc[mi][ni][0] += bv.x + sa.x;
            acc[mi][ni][1] += bv.y + sa.y;
            acc[mi][ni][2] += bv.x + sb.x;
            acc[mi][ni][3] += bv.y + sb.y;
        }
    }
    __syncthreads();
    stageProj(oIdx, 128);
    CP_WAIT0();
    __syncthreads();

    // phase B: acc += proj_o; relu; -> As (half)
#pragma unroll
    for (int mi = 0; mi < 2; mi++) {
        int ra = R0 + mi * 16 + g;
        int rb = ra + 8;
#pragma unroll
        for (int ni = 0; ni < 4; ni++) {
            int c = C0 + ni * 8 + 2 * tg;
            float2 oa = __half22float2(*(const __half2*)(Wb + ra * PADPR + (c >> 1)));
            float2 ob = __half22float2(*(const __half2*)(Wb + rb * PADPR + (c >> 1)));
            As[ra * PADK + (c >> 1)] = pk2(fmaxf(acc[mi][ni][0] + oa.x, 0.f),
                                           fmaxf(acc[mi][ni][1] + oa.y, 0.f));
            As[rb * PADK + (c >> 1)] = pk2(fmaxf(acc[mi][ni][2] + ob.x, 0.f),
                                           fmaxf(acc[mi][ni][3] + ob.y, 0.f));
        }
    }
    __syncthreads();
#pragma unroll
    for (int mi = 0; mi < 2; mi++)
#pragma unroll
        for (int ni = 0; ni < 4; ni++)
#pragma unroll
            for (int q = 0; q < 4; q++) acc[mi][ni][q] = 0.f;

    // GEMM2: chunks 2..7
    for (int i = 2; i < 8; i++) {
        const int b = (i & 1) ^ 1;
        if (i < 7)
            stageW(b ^ 1, wt + (size_t)(3 + ((i - 1) >> 1)) * 16384, (i + 1) & 1);
        mmaChunk(b, (i & 1) * 32);
        if (i < 7) {                       // i==7: no staging pending, epilogue is reg/global-only
            CP_WAIT0();
            __syncthreads();
        }

        if (i & 1) {
            const int nc = (i - 2) >> 1;
            const int boff = nc * 128;
#pragma unroll
            for (int mi = 0; mi < 2; mi++) {
                int ra = R0 + mi * 16 + g;
                int rb = ra + 8;
                int ta = t0 + ra, tb = t0 + rb;
                float* dA;
                float* dB;
                if (nc == 1) { dA = outP + (size_t)ta * 128; dB = outP + (size_t)tb * 128; }
                else {
                    const int* ridx = nc ? oIdx : sIdx;
                    dA = pooled + (size_t)ridx[ra] * 128;
                    dB = pooled + (size_t)ridx[rb] * 128;
                }
#pragma unroll
                for (int ni = 0; ni < 4; ni++) {
                    int cb = C0 + ni * 8;
                    float2 bv = *(const float2*)(b1b + boff + cb + 2 * tg);
                    float p0 = fmaxf(acc[mi][ni][0] + bv.x, 0.f);
                    float p1 = fmaxf(acc[mi][ni][1] + bv.y, 0.f);
                    float q0 = fmaxf(acc[mi][ni][2] + bv.x, 0.f);
                    float q1 = fmaxf(acc[mi][ni][3] + bv.y, 0.f);
                    float pp0 = __shfl_xor_sync(0xFFFFFFFF, p0, 1);
                    float pp1 = __shfl_xor_sync(0xFFFFFFFF, p1, 1);
                    float qq0 = __shfl_xor_sync(0xFFFFFFFF, q0, 1);
                    float qq1 = __shfl_xor_sync(0xFFFFFFFF, q1, 1);
                    if (nc == 1) {
                        if (!(tg & 1)) {
                            if (ta < T) *(float4*)(dA + cb + 2 * tg) = make_float4(p0, p1, pp0, pp1);
                        } else {
                            if (tb < T) *(float4*)(dB + cb + 2 * (tg - 1)) = make_float4(qq0, qq1, q0, q1);
                        }
                    } else {
                        if (!(tg & 1)) {
                            if (ta < T) red_add_v4(dA + cb + 2 * tg, p0, p1, pp0, pp1);
                        } else {
                            if (tb < T) red_add_v4(dB + cb + 2 * (tg - 1), qq0, qq1, q0, q1);
                        }
                    }
                }
            }
            if (i < 7) {
#pragma unroll
                for (int mi = 0; mi < 2; mi++)
#pragma unroll
                    for (int ni = 0; ni < 4; ni++)
#pragma unroll
                        for (int q = 0; q < 4; q++) acc[mi][ni][q] = 0.f;
            }
        }
    }
}

// ================= Kernel P: proj (R14, dead final barrier removed) =================
__global__ __launch_bounds__(256, 3)
void proj_kernel(const float* __restrict__ obj, const __half* __restrict__ wt,
                 __half* __restrict__ proj, int O)
{
    extern __shared__ unsigned smu[];
    unsigned* As = smu;
    unsigned* Wb = smu + MT * PADK;

    const int tid  = threadIdx.x;
    const int lane = tid & 31;
    const int g    = lane >> 2;
    const int tg   = lane & 3;
    const int w    = tid >> 5;
    const int R0   = (w >> 2) * 32;
    const int C0   = (w & 3) * 32;
    const int o0   = blockIdx.x * MT;

    const int rp   = lane & 7;
    const int sel  = lane >> 3;
    const int arow = ((sel & 1) << 3) + rp;
    const int acol = (sel >> 1) << 2;
    const int brow = ((sel >> 1) << 3) + rp;
    const int bcol = (sel & 1) << 2;

    auto stageW = [&](int buf, const __half* tile, int half) {
        unsigned* dstBase = Wb + buf * 128 * PADW2;
#pragma unroll
        for (int p = 0; p < 4; p++) {
            int idx = p * 256 + tid;
            int n = idx >> 3, c8 = idx & 7;
            cp16(dstBase + n * PADW2 + c8 * 4, tile + n * 128 + half * 64 + c8 * 8);
        }
        CP_COMMIT();
    };

    stageW(0, wt, 0);

#pragma unroll
    for (int p = 0; p < 8; p++) {
        int idx = p * 256 + tid;
        int r = idx >> 5, c4 = idx & 31;
        int o = o0 + r;
        float4 v = make_float4(0.f, 0.f, 0.f, 0.f);
        if (o < O) v = *(const float4*)(obj + (size_t)o * 128 + c4 * 4);
        *(uint2*)(As + r * PADK + c4 * 2) = make_uint2(pk2(v.x, v.y), pk2(v.z, v.w));
    }
    CP_WAIT0();
    __syncthreads();

    float acc[2][4][4];
#pragma unroll
    for (int mi = 0; mi < 2; mi++)
#pragma unroll
        for (int ni = 0; ni < 4; ni++)
#pragma unroll
            for (int q = 0; q < 4; q++) acc[mi][ni][q] = 0.f;

    auto mmaChunk = [&](int b, int kwA0) {
        const unsigned* Wu = Wb + b * 128 * PADW2;
#pragma unroll
        for (int ks = 0; ks < 4; ks++) {
            const int kwA = kwA0 + ks * 8;
            const int kwB = ks * 8;
            unsigned a[2][4], bb[2][4];
#pragma unroll
            for (int mi = 0; mi < 2; mi++)
                ldsm_x4(a[mi], As + (R0 + mi * 16 + arow) * PADK + kwA + acol);
#pragma unroll
            for (int j = 0; j < 2; j++)
                ldsm_x4(bb[j], Wu + (C0 + j * 16 + brow) * PADW2 + kwB + bcol);
#pragma unroll
            for (int mi = 0; mi < 2; mi++)
#pragma unroll
                for (int ni = 0; ni < 4; ni++)
                    mma_f16(acc[mi][ni], a[mi], &bb[ni >> 1][(ni & 1) * 2]);
        }
    };

    for (int i = 0; i < 4; i++) {
        if (i < 3) {
            const __half* tile2 = (i + 1) < 2 ? wt : wt + 2 * 16384;
            stageW((i + 1) & 1, tile2, (i + 1) & 1);
        }
        mmaChunk(i & 1, (i & 1) * 32);
        if (i < 3) {                       // i==3: epilogue is reg/global-only
            CP_WAIT0();
            __syncthreads();
        }

        if (i & 1) {
            const int m = i >> 1;
#pragma unroll
            for (int mi = 0; mi < 2; mi++) {
                int ra = R0 + mi * 16 + g;
                int rb = ra + 8;
                int oa = o0 + ra, ob = o0 + rb;
#pragma unroll
                for (int ni = 0; ni < 4; ni++) {
                    int cb = C0 + ni * 8;
                    float p0 = acc[mi][ni][0], p1 = acc[mi][ni][1];
                    float q0 = acc[mi][ni][2], q1 = acc[mi][ni][3];
                    float pp0 = __shfl_xor_sync(0xFFFFFFFF, p0, 1);
                    float pp1 = __shfl_xor_sync(0xFFFFFFFF, p1, 1);
                    float qq0 = __shfl_xor_sync(0xFFFFFFFF, q0, 1);
                    float qq1 = __shfl_xor_sync(0xFFFFFFFF, q1, 1);
                    if (!(tg & 1)) {
                        if (oa < O)
                            *(uint2*)(proj + (size_t)oa * 256 + m * 128 + cb + 2 * tg) =
                                make_uint2(pk2(p0, p1), pk2(pp0, pp1));
                    } else {
                        if (ob < O)
                            *(uint2*)(proj + (size_t)ob * 256 + m * 128 + cb + 2 * (tg - 1)) =
                                make_uint2(pk2(qq0, qq1), pk2(q0, q1));
                    }
                }
            }
            if (i < 3) {
#pragma unroll
                for (int mi = 0; mi < 2; mi++)
#pragma unroll
                    for (int ni = 0; ni < 4; ni++)
#pragma unroll
                        for (int q = 0; q < 4; q++) acc[mi][ni][q] = 0.f;
            }
        }
    }
}

// ---------------- shared m32n64 mainloop for obj (ldmatrix) ----------------
#define MMA_KLOOP(As, Wu, acc, R0, C0, arow, acol, brow, bcol)                  \
    do {                                                                        \
        _Pragma("unroll")                                                       \
        for (int ks = 0; ks < 8; ks++) {                                        \
            const int kw = ks * 8;                                              \
            unsigned a[2][4], bb[4][4];                                         \
            _Pragma("unroll")                                                   \
            for (int mi = 0; mi < 2; mi++)                                      \
                ldsm_x4(a[mi], (As) + ((R0) + mi * 16 + (arow)) * PADK + kw + (acol)); \
            _Pragma("unroll")                                                   \
            for (int j = 0; j < 4; j++)                                         \
                ldsm_x4(bb[j], (Wu) + ((C0) + j * 16 + (brow)) * PADK + kw + (bcol)); \
            _Pragma("unroll")                                                   \
            for (int mi = 0; mi < 2; mi++)                                      \
                _Pragma("unroll")                                               \
                for (int ni = 0; ni < 8; ni++)                                  \
                    mma_f16(acc[mi][ni], a[mi], &bb[ni >> 1][(ni & 1) * 2]);    \
        }                                                                       \
    } while (0)

#define ZERO_ACC8(acc)                                                          \
    do {                                                                        \
        _Pragma("unroll")                                                       \
        for (int mi = 0; mi < 2; mi++)                                          \
            _Pragma("unroll")                                                   \
            for (int ni = 0; ni < 8; ni++)                                      \
                _Pragma("unroll")                                               \
                for (int q = 0; q < 4; q++) acc[mi][ni][q] = 0.f;               \
    } while (0)

// ================= Kernel B: object MLP (R14 m32n64/occ2) =================
__global__ __launch_bounds__(256, 2)
void obj_kernel(const __half* __restrict__ wt,
                const float* __restrict__ b2a, const float* __restrict__ b2b,
                const float* __restrict__ pooled, const float* __restrict__ counts,
                float* __restrict__ outO, int O)
{
    extern __shared__ unsigned smu[];
    unsigned* As = smu;
    unsigned* Wu = smu + 128 * PADK;
    float* invc = (float*)(smu + 2 * 128 * PADK);

    const int tid  = threadIdx.x;
    const int lane = tid & 31;
    const int g    = lane >> 2;
    const int tg   = lane & 3;
    const int w    = tid >> 5;
    const int R0   = (w >> 1) * 32;
    const int C0   = (w & 1) * 64;
    const int o0   = blockIdx.x * 128;

    const int rp   = lane & 7;
    const int sel  = lane >> 3;
    const int arow = ((sel & 1) << 3) + rp;
    const int acol = (sel >> 1) << 2;
    const int brow = ((sel >> 1) << 3) + rp;
    const int bcol = (sel & 1) << 2;

    if (tid < 128) {
        int o = o0 + tid;
        float c = (o < O) ? counts[o] : 1.f;
        c = fminf(fmaxf(c, 1.f), 1000.f);
        invc[tid] = 1.f / c;
    }

    auto stageW = [&](const __half* src) {
        const uint4* s = (const uint4*)src;
#pragma unroll
        for (int p = 0; p < 8; p++) {
            int idx = p * 256 + tid;
            int n = idx >> 4, c = idx & 15;
            *(uint4*)(Wu + n * PADK + c * 4) = s[idx];
        }
    };

    stageW(wt + 6 * 16384);                // w2a^T
    __syncthreads();

#pragma unroll
    for (int p = 0; p < 16; p++) {
        int idx = p * 256 + tid;
        int r = idx >> 5, c4 = idx & 31;
        int o = o0 + r;
        float4 v = make_float4(0.f, 0.f, 0.f, 0.f);
        if (o < O) v = *(const float4*)(pooled + (size_t)o * 128 + c4 * 4);
        float s = invc[r];
        *(uint2*)(As + r * PADK + c4 * 2) =
            make_uint2(pk2(v.x * s, v.y * s), pk2(v.z * s, v.w * s));
    }
    __syncthreads();

    float acc[2][8][4];
    ZERO_ACC8(acc);
    MMA_KLOOP(As, Wu, acc, R0, C0, arow, acol, brow, bcol);
    __syncthreads();

#pragma unroll
    for (int mi = 0; mi < 2; mi++) {
        int ra = R0 + mi * 16 + g;
        int rb = ra + 8;
#pragma unroll
        for (int ni = 0; ni < 8; ni++) {
            int c = C0 + ni * 8 + 2 * tg;
            float2 bv = *(const float2*)(b2a + c);
            As[ra * PADK + (c >> 1)] = pk2(fmaxf(acc[mi][ni][0] + bv.x, 0.f),
                                           fmaxf(acc[mi][ni][1] + bv.y, 0.f));
            As[rb * PADK + (c >> 1)] = pk2(fmaxf(acc[mi][ni][2] + bv.x, 0.f),
                                           fmaxf(acc[mi][ni][3] + bv.y, 0.f));
        }
    }
    stageW(wt + 7 * 16384);
    __syncthreads();

    ZERO_ACC8(acc);
    MMA_KLOOP(As, Wu, acc, R0, C0, arow, acol, brow, bcol);
#pragma unroll
    for (int mi = 0; mi < 2; mi++) {
        int ra = R0 + mi * 16 + g;
        int rb = ra + 8;
        int oa = o0 + ra, ob = o0 + rb;
#pragma unroll
        for (int ni = 0; ni < 8; ni++) {
            int cb = C0 + ni * 8;
            float2 bv = *(const float2*)(b2b + cb + 2 * tg);
            float p0 = fmaxf(acc[mi][ni][0] + bv.x, 0.f);
            float p1 = fmaxf(acc[mi][ni][1] + bv.y, 0.f);
            float q0 = fmaxf(acc[mi][ni][2] + bv.x, 0.f);
            float q1 = fmaxf(acc[mi][ni][3] + bv.y, 0.f);
            float pp0 = __shfl_xor_sync(0xFFFFFFFF, p0, 1);
            float pp1 = __shfl_xor_sync(0xFFFFFFFF, p1, 1);
            float qq0 = __shfl_xor_sync(0xFFFFFFFF, q0, 1);
            float qq1 = __shfl_xor_sync(0xFFFFFFFF, q1, 1);
            if (!(tg & 1)) {
                if (oa < O)
                    *(float4*)(outO + (size_t)oa * 128 + cb + 2 * tg) =
                        make_float4(p0, p1, pp0, pp1);
            } else {
                if (ob < O)
                    *(float4*)(outO + (size_t)ob * 128 + cb + 2 * (tg - 1)) =
                        make_float4(qq0, qq1, q0, q1);
            }
        }
    }
}

// ================= launch =================
extern "C" void kernel_launch(void* const* d_in, const int* in_sizes, int n_in,
                              void* d_out, int out_size)
{
    const float* obj   = (const float*)d_in[0];
    const float* predi = (const float*)d_in[1];
    const int*   edges = (const int*)d_in[2];
    const float* w1a   = (const float*)d_in[3];
    const float* b1a   = (const float*)d_in[4];
    const float* w1b   = (const float*)d_in[5];
    const float* b1b   = (const float*)d_in[6];
    const float* w2a   = (const float*)d_in[7];
    const float* b2a   = (const float*)d_in[8];
    const float* w2b   = (const float*)d_in[9];
    const float* b2b   = (const float*)d_in[10];

    const int O = in_sizes[0] / 128;
    const int T = in_sizes[1] / 128;

    float* outO = (float*)d_out;
    float* outP = outO + (size_t)O * 128;

    float *pooled = nullptr, *counts = nullptr;
    __half *proj = nullptr, *wt = nullptr;
    cudaGetSymbolAddress((void**)&pooled, g_pooled);
    cudaGetSymbolAddress((void**)&counts, g_counts);
    cudaGetSymbolAddress((void**)&proj,   g_proj);
    cudaGetSymbolAddress((void**)&wt,     g_wt);

    cudaMemsetAsync(pooled, 0, (size_t)O * 128 * sizeof(float));
    cudaMemsetAsync(counts, 0, (size_t)O * sizeof(float));

    const size_t smT = (size_t)(MT * PADK + 2 * 128 * PADW2) * 4 + MT * 2 * 4 + 256;
    const size_t smP = (size_t)(MT * PADK + 2 * 128 * PADW2) * 4 + 256;
    const size_t smB = (size_t)(2 * 128 * PADK) * 4 + 512;

    cudaFuncSetAttribute(proj_kernel,   cudaFuncAttributeMaxDynamicSharedMemorySize, (int)smP);
    cudaFuncSetAttribute(triple_kernel, cudaFuncAttributeMaxDynamicSharedMemorySize, (int)smT);
    cudaFuncSetAttribute(obj_kernel,    cudaFuncAttributeMaxDynamicSharedMemorySize, (int)smB);

    prep_kernel<<<8, 256>>>(w1a, w1b, w2a, w2b, wt);
    proj_kernel<<<(O + MT - 1) / MT, 256, smP>>>(obj, wt, proj, O);
    triple_kernel<<<(T + MT - 1) / MT, 256, smT>>>(predi, edges, wt, b1a, b1b, proj,
                                                   outP, pooled, counts, T);
    obj_kernel<<<(O + 127) / 128, 256, smB>>>(wt, b2a, b2b, pooled, counts, outO, O);
}